// round 9
// baseline (speedup 1.0000x reference)
#include <cuda_runtime.h>
#include <math.h>

#define H   1024
#define H2  2048
#define H3  3072
#define SS  4096
#define V   50257

#define NPART 512            // ctx partial chunks (8 rows each)

// ---- scratch (no allocations allowed) ----
__device__ float g_gi[H3];
__device__ float g_gh[H3];
__device__ float g_scores[SS];
__device__ float g_attn[SS];
__device__ float g_y[H2];                  // [h_new, context]
__device__ float4 g_cpart[NPART][H / 4];   // context partials (deterministic)
__device__ float g_lh[V + 16];             // logits, h-half (+bias)
__device__ float g_lc[V + 16];             // logits, context-half
__device__ float g_red[2];                 // max, log(sumexp)

// output layout (tuple order): output[V], context[H], h_new[H], attn[S]
#define OUT_OUTPUT  0
#define OUT_CONTEXT (V)
#define OUT_HNEW    (V + H)
#define OUT_ATTN    (V + 2 * H)

__device__ __forceinline__ float warpReduceSum(float v) {
    #pragma unroll
    for (int o = 16; o > 0; o >>= 1) v += __shfl_down_sync(0xffffffffu, v, o);
    return v;
}
__device__ __forceinline__ float warpReduceMax(float v) {
    #pragma unroll
    for (int o = 16; o > 0; o >>= 1) v = fmaxf(v, __shfl_down_sync(0xffffffffu, v, o));
    return v;
}
__device__ __forceinline__ float dot4(float4 a, float4 b) {
    return a.x * b.x + a.y * b.y + a.z * b.z + a.w * b.w;
}

// K1: gi = w_ih@[emb,ctx] + b_ih ; gh = w_hh@h + b_hh.
// Warp-per-row, 8 rows/block. Blocks [0,384): w_ih. Blocks [384,768): w_hh.
__global__ void __launch_bounds__(256) k_gates(
        const int* __restrict__ word,
        const float* __restrict__ emb,
        const float* __restrict__ ctx,
        const float* __restrict__ w_ih,
        const float* __restrict__ w_hh,
        const float* __restrict__ b_ih,
        const float* __restrict__ b_hh,
        const float* __restrict__ h) {
    __shared__ float4 sv[H2 / 4];
    int b = blockIdx.x;
    int tid = threadIdx.x;
    bool ih = (b < 384);
    if (ih) {
        const float4* e4 = (const float4*)(emb + (size_t)word[0] * H);
        sv[tid] = e4[tid];
        sv[256 + tid] = ((const float4*)ctx)[tid];
    } else {
        sv[tid] = ((const float4*)h)[tid];
    }
    __syncthreads();

    int warp = tid >> 5, lane = tid & 31;
    if (ih) {
        int row = b * 8 + warp;
        const float4* w4 = (const float4*)(w_ih + (size_t)row * H2);
        float acc = 0.f;
        #pragma unroll
        for (int i = 0; i < 16; i++) {
            int j = lane + 32 * i;
            acc += dot4(w4[j], sv[j]);
        }
        acc = warpReduceSum(acc);
        if (lane == 0) g_gi[row] = acc + b_ih[row];
    } else {
        int row = (b - 384) * 8 + warp;
        const float4* w4 = (const float4*)(w_hh + (size_t)row * H);
        float acc = 0.f;
        #pragma unroll
        for (int i = 0; i < 8; i++) {
            int j = lane + 32 * i;
            acc += dot4(w4[j], sv[j]);
        }
        acc = warpReduceSum(acc);
        if (lane == 0) g_gh[row] = acc + b_hh[row];
    }
}

// K2: fused GRU pointwise (recomputed per block into smem) + attention scores.
__global__ void __launch_bounds__(256) k_scores(
        const float* __restrict__ enc,
        const float* __restrict__ h,
        float* __restrict__ out) {
    __shared__ float4 sh[H / 4];
    int tid = threadIdx.x;
    for (int i = tid; i < H; i += 256) {
        float r = 1.f / (1.f + expf(-(g_gi[i]     + g_gh[i])));
        float z = 1.f / (1.f + expf(-(g_gi[H + i] + g_gh[H + i])));
        float n = tanhf(g_gi[2 * H + i] + r * g_gh[2 * H + i]);
        float hn = (1.f - z) * n + z * h[i];
        ((float*)sh)[i] = hn;
        if (blockIdx.x == 0) {
            g_y[i] = hn;
            out[OUT_HNEW + i] = hn;
        }
    }
    __syncthreads();

    int warp = tid >> 5, lane = tid & 31;
    int row = blockIdx.x * 8 + warp;
    const float4* e4 = (const float4*)(enc + (size_t)row * H);
    float acc = 0.f;
    #pragma unroll
    for (int i = 0; i < 8; i++) {
        int j = lane + 32 * i;
        acc += dot4(e4[j], sh[j]);
    }
    acc = warpReduceSum(acc);
    if (lane == 0) g_scores[row] = acc;
}

// K3: softmax over S=4096 (single block). Writes attn output slot.
__global__ void k_softmax(float* __restrict__ out) {
    __shared__ float sred[32];
    __shared__ float sM, sSum;
    int tid = threadIdx.x;
    int wid = tid >> 5, lane = tid & 31;

    float m = -1e30f;
    for (int i = tid; i < SS; i += 1024) m = fmaxf(m, g_scores[i]);
    m = warpReduceMax(m);
    if (lane == 0) sred[wid] = m;
    __syncthreads();
    if (wid == 0) {
        m = sred[lane];
        m = warpReduceMax(m);
        if (lane == 0) sM = m;
    }
    __syncthreads();
    float M = sM;

    float s = 0.f;
    for (int i = tid; i < SS; i += 1024) s += expf(g_scores[i] - M);
    s = warpReduceSum(s);
    if (lane == 0) sred[wid] = s;
    __syncthreads();
    if (wid == 0) {
        s = sred[lane];
        s = warpReduceSum(s);
        if (lane == 0) sSum = s;
    }
    __syncthreads();
    float inv = 1.f / sSum;

    for (int i = tid; i < SS; i += 1024) {
        float a = expf(g_scores[i] - M) * inv;
        g_attn[i] = a;
        out[OUT_ATTN + i] = a;
    }
}

// K4 (side stream): g_lh = out_w[:, 0:H] @ h_new + out_b.
// Warp per row, 8 rows/block, evict-first streaming loads. Launch #4 -> profiled.
__global__ void __launch_bounds__(256) k_logits_h(const float* __restrict__ out_w,
                                                  const float* __restrict__ out_b) {
    __shared__ float4 sy[H / 4];
    for (int j = threadIdx.x; j < H / 4; j += blockDim.x)
        sy[j] = ((const float4*)g_y)[j];
    __syncthreads();

    int warp = threadIdx.x >> 5, lane = threadIdx.x & 31;
    int row = blockIdx.x * 8 + warp;
    if (row >= V) return;

    const float4* w4 = (const float4*)(out_w + (size_t)row * H2);
    float acc = 0.f;
    #pragma unroll
    for (int i = 0; i < 8; i++) {
        int j = lane + 32 * i;
        acc += dot4(__ldcs(w4 + j), sy[j]);
    }
    acc = warpReduceSum(acc);
    if (lane == 0) g_lh[row] = acc + out_b[row];
}

// K5: context partials. 512 blocks x 256 threads, one float4 column per thread.
__global__ void __launch_bounds__(256) k_ctx_part(const float* __restrict__ enc) {
    int c4 = threadIdx.x;
    int s0 = blockIdx.x * 8;
    const float4* e4 = (const float4*)enc;
    float4 acc = make_float4(0.f, 0.f, 0.f, 0.f);
    #pragma unroll
    for (int k = 0; k < 8; k++) {
        float a = g_attn[s0 + k];
        float4 e = e4[(size_t)(s0 + k) * (H / 4) + c4];
        acc.x += a * e.x; acc.y += a * e.y; acc.z += a * e.z; acc.w += a * e.w;
    }
    g_cpart[blockIdx.x][c4] = acc;
}

// K6: sum NPART partials per column (deterministic). Writes context + y[H:2H].
__global__ void __launch_bounds__(256) k_ctx_sum(float* __restrict__ out) {
    int col = blockIdx.x * 256 + threadIdx.x;
    const float* cp = (const float*)g_cpart;
    float a0 = 0.f, a1 = 0.f, a2 = 0.f, a3 = 0.f;
    #pragma unroll 8
    for (int p = 0; p < NPART; p += 4) {
        a0 += cp[(p    ) * H + col];
        a1 += cp[(p + 1) * H + col];
        a2 += cp[(p + 2) * H + col];
        a3 += cp[(p + 3) * H + col];
    }
    float acc = (a0 + a1) + (a2 + a3);
    out[OUT_CONTEXT + col] = acc;
    g_y[H + col] = acc;
}

// K7 (main stream, concurrent with K4): g_lc = out_w[:, H:2H] @ context.
__global__ void __launch_bounds__(256) k_logits_c(const float* __restrict__ out_w) {
    __shared__ float4 sy[H / 4];
    for (int j = threadIdx.x; j < H / 4; j += blockDim.x)
        sy[j] = ((const float4*)(g_y + H))[j];
    __syncthreads();

    int warp = threadIdx.x >> 5, lane = threadIdx.x & 31;
    int row = blockIdx.x * 8 + warp;
    if (row >= V) return;

    const float4* w4 = (const float4*)(out_w + (size_t)row * H2 + H);
    float acc = 0.f;
    #pragma unroll
    for (int i = 0; i < 8; i++) {
        int j = lane + 32 * i;
        acc += dot4(__ldcs(w4 + j), sy[j]);
    }
    acc = warpReduceSum(acc);
    if (lane == 0) g_lc[row] = acc;
}

// K8: log-softmax reduction over g_lh + g_lc (single block, 1024 threads).
__global__ void k_lsm_red() {
    __shared__ float sred[32];
    __shared__ float sM, sSum;
    int tid = threadIdx.x;
    int wid = tid >> 5, lane = tid & 31;

    float m = -1e30f;
    for (int i = tid; i < V; i += 1024) m = fmaxf(m, g_lh[i] + g_lc[i]);
    m = warpReduceMax(m);
    if (lane == 0) sred[wid] = m;
    __syncthreads();
    if (wid == 0) {
        m = sred[lane];
        m = warpReduceMax(m);
        if (lane == 0) sM = m;
    }
    __syncthreads();
    float M = sM;

    float s = 0.f;
    for (int i = tid; i < V; i += 1024) s += expf(g_lh[i] + g_lc[i] - M);
    s = warpReduceSum(s);
    if (lane == 0) sred[wid] = s;
    __syncthreads();
    if (wid == 0) {
        s = sred[lane];
        s = warpReduceSum(s);
        if (lane == 0) sSum = s;
    }
    __syncthreads();
    if (tid == 0) { g_red[0] = M; g_red[1] = logf(sSum); }
}

// K9: output = (lh + lc) - max - log(sumexp)
__global__ void k_lsm_write(float* __restrict__ out) {
    int i = blockIdx.x * blockDim.x + threadIdx.x;
    if (i < V) out[OUT_OUTPUT + i] = g_lh[i] + g_lc[i] - g_red[0] - g_red[1];
}

extern "C" void kernel_launch(void* const* d_in, const int* in_sizes, int n_in,
                              void* d_out, int out_size) {
    const int*   word         = (const int*)d_in[0];
    const float* last_context = (const float*)d_in[1];
    const float* last_hidden  = (const float*)d_in[2];
    const float* enc          = (const float*)d_in[3];
    const float* embedding    = (const float*)d_in[4];
    const float* w_ih         = (const float*)d_in[5];
    const float* w_hh         = (const float*)d_in[6];
    const float* b_ih         = (const float*)d_in[7];
    const float* b_hh         = (const float*)d_in[8];
    const float* out_w        = (const float*)d_in[9];
    const float* out_b        = (const float*)d_in[10];
    float* out = (float*)d_out;

    // One-time (first/correctness call) side-stream + event setup. No device
    // memory is allocated; the same work runs on every call.
    static cudaStream_t s_side = (cudaStream_t)0;
    static cudaEvent_t  s_evFork = (cudaEvent_t)0;
    static cudaEvent_t  s_evH    = (cudaEvent_t)0;
    static int s_init = 0;
    if (!s_init) {
        s_init = 1;
        if (cudaStreamCreateWithFlags(&s_side, cudaStreamNonBlocking) != cudaSuccess)
            s_side = (cudaStream_t)0;
        if (s_side) {
            if (cudaEventCreateWithFlags(&s_evFork, cudaEventDisableTiming) != cudaSuccess ||
                cudaEventCreateWithFlags(&s_evH,   cudaEventDisableTiming) != cudaSuccess)
                s_side = (cudaStream_t)0;
        }
    }

    k_gates  <<<768, 256>>>(word, embedding, last_context, w_ih, w_hh,
                            b_ih, b_hh, last_hidden);
    k_scores <<<512, 256>>>(enc, last_hidden, out);
    k_softmax<<<1, 1024>>>(out);

    if (s_side) {
        // Fork: h-half logits stream on the side stream (submission #4 -> profiled),
        // concurrent with the ctx chain + c-half logits on the main stream.
        cudaEventRecord(s_evFork, 0);
        cudaStreamWaitEvent(s_side, s_evFork, 0);
        k_logits_h<<<(V + 7) / 8, 256, 0, s_side>>>(out_w, out_b);
        cudaEventRecord(s_evH, s_side);

        k_ctx_part<<<NPART, 256>>>(enc);
        k_ctx_sum <<<H / 256, 256>>>(out);
        k_logits_c<<<(V + 7) / 8, 256>>>(out_w);

        cudaStreamWaitEvent(0, s_evH, 0);   // join before the lsm tail
    } else {
        k_logits_h<<<(V + 7) / 8, 256>>>(out_w, out_b);
        k_ctx_part<<<NPART, 256>>>(enc);
        k_ctx_sum <<<H / 256, 256>>>(out);
        k_logits_c<<<(V + 7) / 8, 256>>>(out_w);
    }

    k_lsm_red  <<<1, 1024>>>();
    k_lsm_write<<<(V + 255) / 256, 256>>>(out);
}

// round 10
// speedup vs baseline: 1.0330x; 1.0330x over previous
#include <cuda_runtime.h>
#include <math.h>

#define H   1024
#define H2  2048
#define H3  3072
#define SS  4096
#define V   50257

#define NPART 512            // ctx partial chunks (8 rows each)
#define LOG_BLOCKS ((V + 15) / 16)   // 3142 blocks, 16 rows each (2 per warp)

// ---- scratch (no allocations allowed) ----
__device__ float g_gi[H3];
__device__ float g_gh[H3];
__device__ float g_scores[SS];
__device__ float g_attn[SS];
__device__ float g_y[H2];                  // [h_new, context]
__device__ float4 g_cpart[NPART][H / 4];   // context partials (deterministic)
__device__ float g_lh[V + 16];             // logits, h-half (+bias)
__device__ float g_lc[V + 16];             // logits, context-half
__device__ float g_red[2];                 // max, log(sumexp)

// output layout (tuple order): output[V], context[H], h_new[H], attn[S]
#define OUT_OUTPUT  0
#define OUT_CONTEXT (V)
#define OUT_HNEW    (V + H)
#define OUT_ATTN    (V + 2 * H)

__device__ __forceinline__ float warpReduceSum(float v) {
    #pragma unroll
    for (int o = 16; o > 0; o >>= 1) v += __shfl_down_sync(0xffffffffu, v, o);
    return v;
}
__device__ __forceinline__ float warpReduceMax(float v) {
    #pragma unroll
    for (int o = 16; o > 0; o >>= 1) v = fmaxf(v, __shfl_down_sync(0xffffffffu, v, o));
    return v;
}
__device__ __forceinline__ float dot4(float4 a, float4 b) {
    return a.x * b.x + a.y * b.y + a.z * b.z + a.w * b.w;
}

// K1: gi = w_ih@[emb,ctx] + b_ih ; gh = w_hh@h + b_hh.
// Warp-per-row, 8 rows/block. Plain loads -> weights can stay L2-resident
// across graph replays (only out_w streams evict-first).
__global__ void __launch_bounds__(256) k_gates(
        const int* __restrict__ word,
        const float* __restrict__ emb,
        const float* __restrict__ ctx,
        const float* __restrict__ w_ih,
        const float* __restrict__ w_hh,
        const float* __restrict__ b_ih,
        const float* __restrict__ b_hh,
        const float* __restrict__ h) {
    __shared__ float4 sv[H2 / 4];
    int b = blockIdx.x;
    int tid = threadIdx.x;
    bool ih = (b < 384);
    if (ih) {
        const float4* e4 = (const float4*)(emb + (size_t)word[0] * H);
        sv[tid] = e4[tid];
        sv[256 + tid] = ((const float4*)ctx)[tid];
    } else {
        sv[tid] = ((const float4*)h)[tid];
    }
    __syncthreads();

    int warp = tid >> 5, lane = tid & 31;
    if (ih) {
        int row = b * 8 + warp;
        const float4* w4 = (const float4*)(w_ih + (size_t)row * H2);
        float acc = 0.f;
        #pragma unroll
        for (int i = 0; i < 16; i++) {
            int j = lane + 32 * i;
            acc += dot4(w4[j], sv[j]);
        }
        acc = warpReduceSum(acc);
        if (lane == 0) g_gi[row] = acc + b_ih[row];
    } else {
        int row = (b - 384) * 8 + warp;
        const float4* w4 = (const float4*)(w_hh + (size_t)row * H);
        float acc = 0.f;
        #pragma unroll
        for (int i = 0; i < 8; i++) {
            int j = lane + 32 * i;
            acc += dot4(w4[j], sv[j]);
        }
        acc = warpReduceSum(acc);
        if (lane == 0) g_gh[row] = acc + b_hh[row];
    }
}

// K2: fused GRU pointwise (recomputed per block into smem) + attention scores.
__global__ void __launch_bounds__(256) k_scores(
        const float* __restrict__ enc,
        const float* __restrict__ h,
        float* __restrict__ out) {
    __shared__ float4 sh[H / 4];
    int tid = threadIdx.x;
    for (int i = tid; i < H; i += 256) {
        float r = 1.f / (1.f + expf(-(g_gi[i]     + g_gh[i])));
        float z = 1.f / (1.f + expf(-(g_gi[H + i] + g_gh[H + i])));
        float n = tanhf(g_gi[2 * H + i] + r * g_gh[2 * H + i]);
        float hn = (1.f - z) * n + z * h[i];
        ((float*)sh)[i] = hn;
        if (blockIdx.x == 0) {
            g_y[i] = hn;
            out[OUT_HNEW + i] = hn;
        }
    }
    __syncthreads();

    int warp = tid >> 5, lane = tid & 31;
    int row = blockIdx.x * 8 + warp;
    const float4* e4 = (const float4*)(enc + (size_t)row * H);
    float acc = 0.f;
    #pragma unroll
    for (int i = 0; i < 8; i++) {
        int j = lane + 32 * i;
        acc += dot4(e4[j], sh[j]);
    }
    acc = warpReduceSum(acc);
    if (lane == 0) g_scores[row] = acc;
}

// K3: softmax over S=4096 (single block). Writes attn output slot.
__global__ void k_softmax(float* __restrict__ out) {
    __shared__ float sred[32];
    __shared__ float sM, sSum;
    int tid = threadIdx.x;
    int wid = tid >> 5, lane = tid & 31;

    float m = -1e30f;
    for (int i = tid; i < SS; i += 1024) m = fmaxf(m, g_scores[i]);
    m = warpReduceMax(m);
    if (lane == 0) sred[wid] = m;
    __syncthreads();
    if (wid == 0) {
        m = sred[lane];
        m = warpReduceMax(m);
        if (lane == 0) sM = m;
    }
    __syncthreads();
    float M = sM;

    float s = 0.f;
    for (int i = tid; i < SS; i += 1024) s += expf(g_scores[i] - M);
    s = warpReduceSum(s);
    if (lane == 0) sred[wid] = s;
    __syncthreads();
    if (wid == 0) {
        s = sred[lane];
        s = warpReduceSum(s);
        if (lane == 0) sSum = s;
    }
    __syncthreads();
    float inv = 1.f / sSum;

    for (int i = tid; i < SS; i += 1024) {
        float a = expf(g_scores[i] - M) * inv;
        g_attn[i] = a;
        out[OUT_ATTN + i] = a;
    }
}

// K4 (side stream, forked after k_scores): g_lh = out_w[:, 0:H] @ h_new + b.
// 2 rows per warp -> 16 independent float4 loads in flight (MLP=16, same as
// the fused R2 kernel that hit ~6.3 TB/s). 16 rows/block, 3142 blocks.
__global__ void __launch_bounds__(256) k_logits_h(const float* __restrict__ out_w,
                                                  const float* __restrict__ out_b) {
    __shared__ float4 sy[H / 4];
    {
        int t = threadIdx.x;
        sy[t] = ((const float4*)g_y)[t];
    }
    __syncthreads();

    int warp = threadIdx.x >> 5, lane = threadIdx.x & 31;
    int row0 = blockIdx.x * 16 + warp * 2;
    int row1 = row0 + 1;
    int r0 = row0 < V ? row0 : V - 1;   // clamp: no OOB reads in tail block
    int r1 = row1 < V ? row1 : V - 1;

    const float4* w0 = (const float4*)(out_w + (size_t)r0 * H2);
    const float4* w1 = (const float4*)(out_w + (size_t)r1 * H2);
    float acc0 = 0.f, acc1 = 0.f;
    #pragma unroll
    for (int i = 0; i < 8; i++) {
        int j = lane + 32 * i;
        float4 a0 = __ldcs(w0 + j);
        float4 a1 = __ldcs(w1 + j);
        float4 y  = sy[j];
        acc0 += dot4(a0, y);
        acc1 += dot4(a1, y);
    }
    acc0 = warpReduceSum(acc0);
    acc1 = warpReduceSum(acc1);
    if (lane == 0) {
        if (row0 < V) g_lh[row0] = acc0 + out_b[row0];
        if (row1 < V) g_lh[row1] = acc1 + out_b[row1];
    }
}

// K5: context partials. 512 blocks x 256 threads, one float4 column per thread.
__global__ void __launch_bounds__(256) k_ctx_part(const float* __restrict__ enc) {
    int c4 = threadIdx.x;
    int s0 = blockIdx.x * 8;
    const float4* e4 = (const float4*)enc;
    float4 acc = make_float4(0.f, 0.f, 0.f, 0.f);
    #pragma unroll
    for (int k = 0; k < 8; k++) {
        float a = g_attn[s0 + k];
        float4 e = e4[(size_t)(s0 + k) * (H / 4) + c4];
        acc.x += a * e.x; acc.y += a * e.y; acc.z += a * e.z; acc.w += a * e.w;
    }
    g_cpart[blockIdx.x][c4] = acc;
}

// K6: sum NPART partials per column (deterministic). Writes context + y[H:2H].
__global__ void __launch_bounds__(256) k_ctx_sum(float* __restrict__ out) {
    int col = blockIdx.x * 256 + threadIdx.x;
    const float* cp = (const float*)g_cpart;
    float a0 = 0.f, a1 = 0.f, a2 = 0.f, a3 = 0.f;
    #pragma unroll 8
    for (int p = 0; p < NPART; p += 4) {
        a0 += cp[(p    ) * H + col];
        a1 += cp[(p + 1) * H + col];
        a2 += cp[(p + 2) * H + col];
        a3 += cp[(p + 3) * H + col];
    }
    float acc = (a0 + a1) + (a2 + a3);
    out[OUT_CONTEXT + col] = acc;
    g_y[H + col] = acc;
}

// K7 (main stream): g_lc = out_w[:, H:2H] @ context. Same 2-rows-per-warp.
__global__ void __launch_bounds__(256) k_logits_c(const float* __restrict__ out_w) {
    __shared__ float4 sy[H / 4];
    {
        int t = threadIdx.x;
        sy[t] = ((const float4*)(g_y + H))[t];
    }
    __syncthreads();

    int warp = threadIdx.x >> 5, lane = threadIdx.x & 31;
    int row0 = blockIdx.x * 16 + warp * 2;
    int row1 = row0 + 1;
    int r0 = row0 < V ? row0 : V - 1;
    int r1 = row1 < V ? row1 : V - 1;

    const float4* w0 = (const float4*)(out_w + (size_t)r0 * H2 + H);
    const float4* w1 = (const float4*)(out_w + (size_t)r1 * H2 + H);
    float acc0 = 0.f, acc1 = 0.f;
    #pragma unroll
    for (int i = 0; i < 8; i++) {
        int j = lane + 32 * i;
        float4 a0 = __ldcs(w0 + j);
        float4 a1 = __ldcs(w1 + j);
        float4 y  = sy[j];
        acc0 += dot4(a0, y);
        acc1 += dot4(a1, y);
    }
    acc0 = warpReduceSum(acc0);
    acc1 = warpReduceSum(acc1);
    if (lane == 0) {
        if (row0 < V) g_lc[row0] = acc0;
        if (row1 < V) g_lc[row1] = acc1;
    }
}

// K8: log-softmax reduction over g_lh + g_lc (single block, 1024 threads).
__global__ void k_lsm_red() {
    __shared__ float sred[32];
    __shared__ float sM, sSum;
    int tid = threadIdx.x;
    int wid = tid >> 5, lane = tid & 31;

    float m = -1e30f;
    for (int i = tid; i < V; i += 1024) m = fmaxf(m, g_lh[i] + g_lc[i]);
    m = warpReduceMax(m);
    if (lane == 0) sred[wid] = m;
    __syncthreads();
    if (wid == 0) {
        m = sred[lane];
        m = warpReduceMax(m);
        if (lane == 0) sM = m;
    }
    __syncthreads();
    float M = sM;

    float s = 0.f;
    for (int i = tid; i < V; i += 1024) s += expf(g_lh[i] + g_lc[i] - M);
    s = warpReduceSum(s);
    if (lane == 0) sred[wid] = s;
    __syncthreads();
    if (wid == 0) {
        s = sred[lane];
        s = warpReduceSum(s);
        if (lane == 0) sSum = s;
    }
    __syncthreads();
    if (tid == 0) { g_red[0] = M; g_red[1] = logf(sSum); }
}

// K9: output = (lh + lc) - max - log(sumexp)
__global__ void k_lsm_write(float* __restrict__ out) {
    int i = blockIdx.x * blockDim.x + threadIdx.x;
    if (i < V) out[OUT_OUTPUT + i] = g_lh[i] + g_lc[i] - g_red[0] - g_red[1];
}

extern "C" void kernel_launch(void* const* d_in, const int* in_sizes, int n_in,
                              void* d_out, int out_size) {
    const int*   word         = (const int*)d_in[0];
    const float* last_context = (const float*)d_in[1];
    const float* last_hidden  = (const float*)d_in[2];
    const float* enc          = (const float*)d_in[3];
    const float* embedding    = (const float*)d_in[4];
    const float* w_ih         = (const float*)d_in[5];
    const float* w_hh         = (const float*)d_in[6];
    const float* b_ih         = (const float*)d_in[7];
    const float* b_hh         = (const float*)d_in[8];
    const float* out_w        = (const float*)d_in[9];
    const float* out_b        = (const float*)d_in[10];
    float* out = (float*)d_out;

    // One-time side-stream + event setup (no device memory involved).
    static cudaStream_t s_side = (cudaStream_t)0;
    static cudaEvent_t  s_evFork = (cudaEvent_t)0;
    static cudaEvent_t  s_evH    = (cudaEvent_t)0;
    static int s_init = 0;
    if (!s_init) {
        s_init = 1;
        if (cudaStreamCreateWithFlags(&s_side, cudaStreamNonBlocking) != cudaSuccess)
            s_side = (cudaStream_t)0;
        if (s_side) {
            if (cudaEventCreateWithFlags(&s_evFork, cudaEventDisableTiming) != cudaSuccess ||
                cudaEventCreateWithFlags(&s_evH,   cudaEventDisableTiming) != cudaSuccess)
                s_side = (cudaStream_t)0;
        }
    }

    k_gates  <<<768, 256>>>(word, embedding, last_context, w_ih, w_hh,
                            b_ih, b_hh, last_hidden);
    k_scores <<<512, 256>>>(enc, last_hidden, out);

    if (s_side) {
        // Fork right after scores: logits_h needs only h_new (g_y[0:H]).
        cudaEventRecord(s_evFork, 0);
        k_softmax<<<1, 1024>>>(out);                       // launch #3

        cudaStreamWaitEvent(s_side, s_evFork, 0);
        k_logits_h<<<LOG_BLOCKS, 256, 0, s_side>>>(out_w, out_b);  // #4 -> profiled
        cudaEventRecord(s_evH, s_side);

        k_ctx_part<<<NPART, 256>>>(enc);
        k_ctx_sum <<<H / 256, 256>>>(out);
        k_logits_c<<<LOG_BLOCKS, 256>>>(out_w);

        cudaStreamWaitEvent(0, s_evH, 0);   // join before the lsm tail
    } else {
        k_softmax <<<1, 1024>>>(out);
        k_logits_h<<<LOG_BLOCKS, 256>>>(out_w, out_b);
        k_ctx_part<<<NPART, 256>>>(enc);
        k_ctx_sum <<<H / 256, 256>>>(out);
        k_logits_c<<<LOG_BLOCKS, 256>>>(out_w);
    }

    k_lsm_red  <<<1, 1024>>>();
    k_lsm_write<<<(V + 255) / 256, 256>>>(out);
}

// round 12
// speedup vs baseline: 1.0428x; 1.0095x over previous
#include <cuda_runtime.h>
#include <math.h>

#define H   1024
#define H2  2048
#define H3  3072
#define SS  4096
#define V   50257
#define VPAD 50264           // 6283 blocks * 8 rows, divisible by 4

#define NPART 512            // ctx partial chunks (8 rows each)

// ---- scratch (no allocations allowed) ----
__device__ float g_gi[H3];
__device__ float g_gh[H3];
__device__ float g_scores[SS];
__device__ float g_attn[SS];
__device__ float g_y[H2];                  // [h_new, context]
__device__ float4 g_cpart[NPART][H / 4];   // context partials (deterministic)
__device__ float g_logits[VPAD + 8];
__device__ float g_red[2];                 // max, log(sumexp)

// output layout (tuple order): output[V], context[H], h_new[H], attn[S]
#define OUT_OUTPUT  0
#define OUT_CONTEXT (V)
#define OUT_HNEW    (V + H)
#define OUT_ATTN    (V + 2 * H)

__device__ __forceinline__ float warpReduceSum(float v) {
    #pragma unroll
    for (int o = 16; o > 0; o >>= 1) v += __shfl_down_sync(0xffffffffu, v, o);
    return v;
}
__device__ __forceinline__ float warpReduceMax(float v) {
    #pragma unroll
    for (int o = 16; o > 0; o >>= 1) v = fmaxf(v, __shfl_down_sync(0xffffffffu, v, o));
    return v;
}
__device__ __forceinline__ float dot4(float4 a, float4 b) {
    return a.x * b.x + a.y * b.y + a.z * b.z + a.w * b.w;
}

// K1: gi = w_ih@[emb,ctx] + b_ih ; gh = w_hh@h + b_hh.
// Warp-per-row, 8 rows/block. Plain loads -> weights may stay L2-resident
// across graph replays (only out_w streams evict-first).
__global__ void __launch_bounds__(256) k_gates(
        const int* __restrict__ word,
        const float* __restrict__ emb,
        const float* __restrict__ ctx,
        const float* __restrict__ w_ih,
        const float* __restrict__ w_hh,
        const float* __restrict__ b_ih,
        const float* __restrict__ b_hh,
        const float* __restrict__ h) {
    __shared__ float4 sv[H2 / 4];
    int b = blockIdx.x;
    int tid = threadIdx.x;
    bool ih = (b < 384);
    if (ih) {
        const float4* e4 = (const float4*)(emb + (size_t)word[0] * H);
        sv[tid] = e4[tid];
        sv[256 + tid] = ((const float4*)ctx)[tid];
    } else {
        sv[tid] = ((const float4*)h)[tid];
    }
    __syncthreads();

    int warp = tid >> 5, lane = tid & 31;
    if (ih) {
        int row = b * 8 + warp;
        const float4* w4 = (const float4*)(w_ih + (size_t)row * H2);
        float acc = 0.f;
        #pragma unroll
        for (int i = 0; i < 16; i++) {
            int j = lane + 32 * i;
            acc += dot4(w4[j], sv[j]);
        }
        acc = warpReduceSum(acc);
        if (lane == 0) g_gi[row] = acc + b_ih[row];
    } else {
        int row = (b - 384) * 8 + warp;
        const float4* w4 = (const float4*)(w_hh + (size_t)row * H);
        float acc = 0.f;
        #pragma unroll
        for (int i = 0; i < 8; i++) {
            int j = lane + 32 * i;
            acc += dot4(w4[j], sv[j]);
        }
        acc = warpReduceSum(acc);
        if (lane == 0) g_gh[row] = acc + b_hh[row];
    }
}

// K2: fused GRU pointwise (recomputed per block into smem) + attention scores.
// 2 rows per warp (MLP=16), 16 rows/block, 256 blocks. Block 0 publishes h_new.
__global__ void __launch_bounds__(256) k_scores(
        const float* __restrict__ enc,
        const float* __restrict__ h,
        float* __restrict__ out) {
    __shared__ float4 sh[H / 4];
    int tid = threadIdx.x;
    for (int i = tid; i < H; i += 256) {
        float r = 1.f / (1.f + expf(-(g_gi[i]     + g_gh[i])));
        float z = 1.f / (1.f + expf(-(g_gi[H + i] + g_gh[H + i])));
        float n = tanhf(g_gi[2 * H + i] + r * g_gh[2 * H + i]);
        float hn = (1.f - z) * n + z * h[i];
        ((float*)sh)[i] = hn;
        if (blockIdx.x == 0) {
            g_y[i] = hn;
            out[OUT_HNEW + i] = hn;
        }
    }
    __syncthreads();

    int warp = tid >> 5, lane = tid & 31;
    int row0 = blockIdx.x * 16 + warp * 2;
    const float4* e0 = (const float4*)(enc + (size_t)row0 * H);
    const float4* e1 = (const float4*)(enc + (size_t)(row0 + 1) * H);
    float acc0 = 0.f, acc1 = 0.f;
    #pragma unroll
    for (int i = 0; i < 8; i++) {
        int j = lane + 32 * i;
        float4 y = sh[j];
        acc0 += dot4(e0[j], y);
        acc1 += dot4(e1[j], y);
    }
    acc0 = warpReduceSum(acc0);
    acc1 = warpReduceSum(acc1);
    if (lane == 0) {
        g_scores[row0]     = acc0;
        g_scores[row0 + 1] = acc1;
    }
}

// K3: softmax over S=4096 (single block). Writes attn output slot.
__global__ void k_softmax(float* __restrict__ out) {
    __shared__ float sred[32];
    __shared__ float sM, sSum;
    int tid = threadIdx.x;
    int wid = tid >> 5, lane = tid & 31;

    float m = -1e30f;
    for (int i = tid; i < SS; i += 1024) m = fmaxf(m, g_scores[i]);
    m = warpReduceMax(m);
    if (lane == 0) sred[wid] = m;
    __syncthreads();
    if (wid == 0) {
        m = sred[lane];
        m = warpReduceMax(m);
        if (lane == 0) sM = m;
    }
    __syncthreads();
    float M = sM;

    float s = 0.f;
    for (int i = tid; i < SS; i += 1024) s += expf(g_scores[i] - M);
    s = warpReduceSum(s);
    if (lane == 0) sred[wid] = s;
    __syncthreads();
    if (wid == 0) {
        s = sred[lane];
        s = warpReduceSum(s);
        if (lane == 0) sSum = s;
    }
    __syncthreads();
    float inv = 1.f / sSum;

    for (int i = tid; i < SS; i += 1024) {
        float a = expf(g_scores[i] - M) * inv;
        g_attn[i] = a;
        out[OUT_ATTN + i] = a;
    }
}

// K4: context partials. 512 blocks x 256 threads, one float4 column per thread.
__global__ void __launch_bounds__(256) k_ctx_part(const float* __restrict__ enc) {
    int c4 = threadIdx.x;
    int s0 = blockIdx.x * 8;
    const float4* e4 = (const float4*)enc;
    float4 acc = make_float4(0.f, 0.f, 0.f, 0.f);
    #pragma unroll
    for (int k = 0; k < 8; k++) {
        float a = g_attn[s0 + k];
        float4 e = e4[(size_t)(s0 + k) * (H / 4) + c4];
        acc.x += a * e.x; acc.y += a * e.y; acc.z += a * e.z; acc.w += a * e.w;
    }
    g_cpart[blockIdx.x][c4] = acc;
}

// K5: sum NPART partials per column (deterministic). Writes context + y[H:2H].
__global__ void __launch_bounds__(256) k_ctx_sum(float* __restrict__ out) {
    int col = blockIdx.x * 256 + threadIdx.x;
    const float* cp = (const float*)g_cpart;
    float a0 = 0.f, a1 = 0.f, a2 = 0.f, a3 = 0.f;
    #pragma unroll 8
    for (int p = 0; p < NPART; p += 4) {
        a0 += cp[(p    ) * H + col];
        a1 += cp[(p + 1) * H + col];
        a2 += cp[(p + 2) * H + col];
        a3 += cp[(p + 3) * H + col];
    }
    float acc = (a0 + a1) + (a2 + a3);
    out[OUT_CONTEXT + col] = acc;
    g_y[H + col] = acc;
}

// K6: FUSED logits = out_w @ y + out_b. Warp per row, 8 rows/block: one
// sequential pass over the full 8KB row, 16 independent float4 loads per
// lane (MLP=16), evict-first streaming. Pad rows [V,VPAD) get -INF.
__global__ void __launch_bounds__(256) k_logits(const float* __restrict__ out_w,
                                                const float* __restrict__ out_b) {
    __shared__ float4 sy[H2 / 4];
    for (int j = threadIdx.x; j < H2 / 4; j += blockDim.x)
        sy[j] = ((const float4*)g_y)[j];
    __syncthreads();

    int warp = threadIdx.x >> 5, lane = threadIdx.x & 31;
    int row = blockIdx.x * 8 + warp;

    if (row < V) {
        const float4* w4 = (const float4*)(out_w + (size_t)row * H2);
        float acc = 0.f;
        #pragma unroll
        for (int i = 0; i < 16; i++) {
            int j = lane + 32 * i;
            acc += dot4(__ldcs(w4 + j), sy[j]);
        }
        acc = warpReduceSum(acc);
        if (lane == 0) g_logits[row] = acc + out_b[row];
    } else if (lane == 0) {
        g_logits[row] = -INFINITY;     // pad rows [V, VPAD)
    }
}

// K7: log-softmax reduction (single block, 1024 threads, float4 over VPAD).
__global__ void k_lsm_red() {
    __shared__ float sred[32];
    __shared__ float sM, sSum;
    int tid = threadIdx.x;
    int wid = tid >> 5, lane = tid & 31;
    const float4* l4 = (const float4*)g_logits;

    float m = -INFINITY;
    for (int i = tid; i < VPAD / 4; i += 1024) {
        float4 v = l4[i];
        m = fmaxf(m, fmaxf(fmaxf(v.x, v.y), fmaxf(v.z, v.w)));
    }
    m = warpReduceMax(m);
    if (lane == 0) sred[wid] = m;
    __syncthreads();
    if (wid == 0) {
        m = sred[lane];
        m = warpReduceMax(m);
        if (lane == 0) sM = m;
    }
    __syncthreads();
    float M = sM;

    float s = 0.f;
    for (int i = tid; i < VPAD / 4; i += 1024) {
        float4 v = l4[i];
        s += expf(v.x - M) + expf(v.y - M) + expf(v.z - M) + expf(v.w - M);
    }
    s = warpReduceSum(s);
    if (lane == 0) sred[wid] = s;
    __syncthreads();
    if (wid == 0) {
        s = sred[lane];
        s = warpReduceSum(s);
        if (lane == 0) sSum = s;
    }
    __syncthreads();
    if (tid == 0) { g_red[0] = M; g_red[1] = logf(sSum); }
}

// K8: output = logits - max - log(sumexp). float4 main body + scalar tail.
__global__ void k_lsm_write(float* __restrict__ out) {
    int i = blockIdx.x * blockDim.x + threadIdx.x;
    float c = g_red[0] + g_red[1];
    const float4* l4 = (const float4*)g_logits;
    if (i < V / 4) {
        float4 v = l4[i];
        float4 r = make_float4(v.x - c, v.y - c, v.z - c, v.w - c);
        ((float4*)(out + OUT_OUTPUT))[i] = r;
    } else {
        int k = (V / 4) * 4 + (i - V / 4);   // tail elements
        if (k < V && i < V / 4 + 4)
            out[OUT_OUTPUT + k] = g_logits[k] - c;
    }
}

extern "C" void kernel_launch(void* const* d_in, const int* in_sizes, int n_in,
                              void* d_out, int out_size) {
    const int*   word         = (const int*)d_in[0];
    const float* last_context = (const float*)d_in[1];
    const float* last_hidden  = (const float*)d_in[2];
    const float* enc          = (const float*)d_in[3];
    const float* embedding    = (const float*)d_in[4];
    const float* w_ih         = (const float*)d_in[5];
    const float* w_hh         = (const float*)d_in[6];
    const float* b_ih         = (const float*)d_in[7];
    const float* b_hh         = (const float*)d_in[8];
    const float* out_w        = (const float*)d_in[9];
    const float* out_b        = (const float*)d_in[10];
    float* out = (float*)d_out;

    k_gates    <<<768, 256>>>(word, embedding, last_context, w_ih, w_hh,
                              b_ih, b_hh, last_hidden);
    k_scores   <<<SS / 16, 256>>>(enc, last_hidden, out);
    k_softmax  <<<1, 1024>>>(out);
    k_ctx_part <<<NPART, 256>>>(enc);
    k_ctx_sum  <<<H / 256, 256>>>(out);
    k_logits   <<<VPAD / 8, 256>>>(out_w, out_b);
    k_lsm_red  <<<1, 1024>>>();
    k_lsm_write<<<(V / 4 + 4 + 255) / 256, 256>>>(out);
}